// round 7
// baseline (speedup 1.0000x reference)
#include <cuda_runtime.h>
#include <cstdint>
#include <math.h>

#define NN 5
#define BB 4
#define CC 256
#define SSZ 1024
#define NCH 32              // K=256 in k8 chunks
#define STG_FLT 10752       // floats per stage: A/W 8192 + B 2560
#define NSTAGE 3
#define SMEM_BYTES (NSTAGE * STG_FLT * 4)   // 129024

// ---- device-global scratch (allocation-free rule) ----
// A/W blob, fragment-ordered: [i][chunk][part(4: Ah,Al,Wh,Wl)][m16 t(16)][lane(32)][q(4)]
__device__ float g_Aw[NN * NCH * 8192];
// B blob, fragment-ordered: [j][b][stile(32)][chunk][hl(2)][n8(4)][lane(32)][q(2)]
__device__ float g_Bf[(size_t)NN * BB * 32 * NCH * 512];

__device__ __forceinline__ float hi10(float v) {   // tf32-exact high part
    return __uint_as_float(__float_as_uint(v) & 0xFFFFE000u);
}
__device__ __forceinline__ float to_tf32(float v) {
    uint32_t u;
    asm("cvt.rna.tf32.f32 %0, %1;" : "=r"(u) : "f"(v));
    return __uint_as_float(u);
}
__device__ __forceinline__ uint32_t smem_to_u32(const void* p) {
    uint32_t a;
    asm("{ .reg .u64 t; cvta.to.shared.u64 t, %1; cvt.u32.u64 %0, t; }" : "=r"(a) : "l"(p));
    return a;
}

#define MMA(d, a, b)                                                              \
    asm volatile(                                                                 \
        "mma.sync.aligned.m16n8k8.row.col.f32.tf32.tf32.f32 "                     \
        "{%0,%1,%2,%3},{%4,%5,%6,%7},{%8,%9},{%0,%1,%2,%3};"                      \
        : "+f"((d)[0]), "+f"((d)[1]), "+f"((d)[2]), "+f"((d)[3])                  \
        : "r"((a).x), "r"((a).y), "r"((a).z), "r"((a).w), "r"((b).x), "r"((b).y))

// ---- prep 1: conv_w -> fragment-ordered split A(=W1+W2) and W2 ----
__global__ void prep_w(const float* __restrict__ conv_w) {
    int g = blockIdx.x * 256 + threadIdx.x;
    if (g >= NN * NCH * 16 * 32 * 4) return;
    int q = g & 3, lane = (g >> 2) & 31, t = (g >> 7) & 15;
    int chunk = (g >> 11) & 31, i = g >> 16;
    int c = t * 16 + (lane >> 2) + (q & 1) * 8;
    int k = chunk * 8 + (lane & 3) + (q >> 1) * 4;
    float w1 = conv_w[((i * CC + c) << 9) + k];
    float w2 = conv_w[((i * CC + c) << 9) + CC + k];
    float a = w1 + w2;
    float ah = hi10(a), al = to_tf32(a - ah);
    float wh = hi10(w2), wl = to_tf32(w2 - wh);
    size_t base = (((size_t)(i * NCH + chunk) * 4) * 16 + t) * 32 * 4 + lane * 4 + q;
    // parts stride = 16*32*4 = 2048 floats
    g_Aw[base]          = ah;
    g_Aw[base + 2048]   = al;
    g_Aw[base + 4096]   = wh;
    g_Aw[base + 6144]   = wl;
}

// ---- prep 2: x -> fragment-ordered split B ----
__global__ void prep_x(const float* __restrict__ x) {
    int g = blockIdx.x * 256 + threadIdx.x;
    if (g >= NN * BB * 32 * NCH * 4 * 32 * 2) return;
    int q = g & 1, lane = (g >> 1) & 31, n8 = (g >> 6) & 3;
    int chunk = (g >> 8) & 31, stile = (g >> 13) & 31;
    int b = (g >> 18) & 3, j = g >> 20;
    int k = chunk * 8 + (lane & 3) + q * 4;
    int s = stile * 32 + n8 * 8 + (lane >> 2);
    float v = x[(size_t)((j * BB + b) * CC + k) * SSZ + s];
    float h = hi10(v), l = to_tf32(v - h);
    size_t base = (size_t)(((j * BB + b) * 32 + stile) * NCH + chunk) * 512
                + (n8 * 32 + lane) * 2 + q;
    g_Bf[base]       = h;   // hl = 0
    g_Bf[base + 256] = l;   // hl = 1
}

// ---- main fused kernel: 384 threads, 12 warps = (jz 0..5) x (m-half) ----
__device__ __forceinline__ void issue_chunk(int kc, int ks, int tid, uint32_t smem_u32,
                                            const float* __restrict__ baseA,
                                            const float* __restrict__ baseB) {
#pragma unroll
    for (int r = 0; r < 7; r++) {
        int g = r * 384 + tid;          // 0..2687, 16B each
        const float* src;
        if (g < 2048) {
            src = baseA + (size_t)kc * 8192 + g * 4;
        } else {
            int gb = g - 2048;
            int j = gb >> 7;
            src = baseB + (size_t)j * (BB * 32 * NCH * 512) + (size_t)kc * 512 + (gb & 127) * 4;
        }
        uint32_t dst = smem_u32 + (uint32_t)(ks * STG_FLT + g * 4) * 4u;
        asm volatile("cp.async.cg.shared.global [%0], [%1], 16;" :: "r"(dst), "l"(src) : "memory");
    }
    asm volatile("cp.async.commit_group;" ::: "memory");
}

__global__ __launch_bounds__(384, 1) void fused_mma(
    const float* __restrict__ x, const float* __restrict__ w5,
    const float* __restrict__ conv_b, float* __restrict__ out) {
    extern __shared__ float sm[];
    const uint32_t smem_u32 = smem_to_u32(sm);
    const int tid = threadIdx.x, wid = tid >> 5, lane = tid & 31;
    const int bx = blockIdx.x;
    const int i = bx >> 7;             // 0..4
    const int b = (bx >> 5) & 3;       // 0..3
    const int stile = bx & 31;         // 0..31 (32 s per tile)
    const int s0 = stile * 32;

    const int jz = wid >> 1;           // 0..5 (5 = Z term)
    const int mh = wid & 1;            // m-half: c rows [mh*128, mh*128+128)
    const int jsel = (jz < 5) ? jz : i;

    const float* baseA = g_Aw + (size_t)i * NCH * 8192;
    const float* baseB = g_Bf + (size_t)((b * 32 + stile) * NCH) * 512;

    float acc[8][4][4];
#pragma unroll
    for (int t = 0; t < 8; t++)
#pragma unroll
        for (int n8 = 0; n8 < 4; n8++)
#pragma unroll
            for (int r = 0; r < 4; r++) acc[t][n8][r] = 0.0f;

    issue_chunk(0, 0, tid, smem_u32, baseA, baseB);
    issue_chunk(1, 1, tid, smem_u32, baseA, baseB);

    const int aofs = (jz == 5) ? 4096 : 0;     // Wh/Wl for the Z term
    const int bofs = 8192 + jsel * 512;

#pragma unroll 1
    for (int kc = 0; kc < NCH; kc++) {
        if (kc + 2 < NCH) {
            issue_chunk(kc + 2, (kc + 2) % 3, tid, smem_u32, baseA, baseB);
            asm volatile("cp.async.wait_group 2;" ::: "memory");
        } else if (kc + 1 < NCH) {
            asm volatile("cp.async.wait_group 1;" ::: "memory");
        } else {
            asm volatile("cp.async.wait_group 0;" ::: "memory");
        }
        __syncthreads();

        const float* st = sm + (kc % 3) * STG_FLT;
        uint2 bh[4], bl[4];
#pragma unroll
        for (int n8 = 0; n8 < 4; n8++) {
            bh[n8] = *(const uint2*)&st[bofs + (n8 * 32 + lane) * 2];
            bl[n8] = *(const uint2*)&st[bofs + 256 + (n8 * 32 + lane) * 2];
        }
#pragma unroll
        for (int t = 0; t < 8; t++) {
            int row = (mh * 8 + t) * 32 + lane;
            uint4 ah = *(const uint4*)&st[aofs + row * 4];
            uint4 al = *(const uint4*)&st[aofs + 2048 + row * 4];
#pragma unroll
            for (int n8 = 0; n8 < 4; n8++) {
                MMA(acc[t][n8], ah, bh[n8]);
                MMA(acc[t][n8], al, bh[n8]);
                MMA(acc[t][n8], ah, bl[n8]);
            }
        }
        __syncthreads();
    }

    // ---- epilogue: two phases (one per m-half), accums staged through smem ----
    float wrow[NN];
#pragma unroll
    for (int j = 0; j < NN; j++) wrow[j] = w5[i * NN + j];

#pragma unroll 1
    for (int ph = 0; ph < 2; ph++) {
        if (mh == ph) {
            // store this warp's 128x32 tile into sm[jz*4096 + c_local*32 + s_local]
#pragma unroll
            for (int t = 0; t < 8; t++) {
#pragma unroll
                for (int n8 = 0; n8 < 4; n8++) {
                    int c0 = t * 16 + (lane >> 2);
                    int s = n8 * 8 + (lane & 3) * 2;
                    *(float2*)&sm[jz * 4096 + c0 * 32 + s] =
                        make_float2(acc[t][n8][0], acc[t][n8][1]);
                    *(float2*)&sm[jz * 4096 + (c0 + 8) * 32 + s] =
                        make_float2(acc[t][n8][2], acc[t][n8][3]);
                }
            }
        }
        __syncthreads();

#pragma unroll 1
        for (int e = tid; e < 4096; e += 384) {
            int s_l = e & 31, c_l = e >> 5;
            int c = ph * 128 + c_l;
            float z = sm[5 * 4096 + c_l * 32 + s_l];
            float bic = conv_b[i * CC + c];
            float num = 0.0f, n2 = 0.0f;
#pragma unroll
            for (int j = 0; j < NN; j++) {
                float xx = x[(size_t)((j * BB + b) * CC + c) * SSZ + s0 + s_l];
                float y = sm[j * 4096 + c_l * 32 + s_l];
                float d = xx - (y + z + bic);
                float tt = d * wrow[j];
                float ee = 1.0f / (1.0f + expf(-tt));
                ee = (ee > 0.3f) ? ee : 0.0f;
                n2 = fmaf(ee, ee, n2);
                num = fmaf(ee, xx, num);
            }
            out[(size_t)((i * BB + b) * CC + c) * SSZ + s0 + s_l] =
                (n2 > 0.0f) ? num * rsqrtf(n2) : 0.0f;
        }
        __syncthreads();
    }
}

extern "C" void kernel_launch(void* const* d_in, const int* in_sizes, int n_in,
                              void* d_out, int out_size) {
    const float* x = nullptr;
    const float* w = nullptr;
    const float* conv_w = nullptr;
    const float* conv_b = nullptr;
    for (int t = 0; t < n_in; t++) {
        switch (in_sizes[t]) {
            case 5242880: x = (const float*)d_in[t]; break;
            case 25:      w = (const float*)d_in[t]; break;
            case 655360:  conv_w = (const float*)d_in[t]; break;
            case 1280:    conv_b = (const float*)d_in[t]; break;
            default: break;
        }
    }
    float* out = (float*)d_out;

    static bool attr_set = false;
    if (!attr_set) {
        cudaFuncSetAttribute(fused_mma, cudaFuncAttributeMaxDynamicSharedMemorySize, SMEM_BYTES);
        attr_set = true;
    }

    prep_w<<<(NN * NCH * 16 * 32 * 4 + 255) / 256, 256>>>(conv_w);
    prep_x<<<(NN * BB * 32 * NCH * 4 * 32 * 2 + 255) / 256, 256>>>(x);
    fused_mma<<<NN * BB * 32, 384, SMEM_BYTES>>>(x, w, conv_b, out);
}

// round 8
// speedup vs baseline: 1.0460x; 1.0460x over previous
#include <cuda_runtime.h>
#include <cuda_fp16.h>
#include <cstdint>
#include <math.h>

#define NN 5
#define BB 4
#define CC 256
#define SSZ 1024
#define NCH 16                 // K=256 in k16 chunks
#define STG_B 26624            // bytes/stage: A 16384 + B 10240
#define SMEM_BYTES 104448      // max(3*STG_B=79872, epilogue 6*128*34*4=104448)
#define EPJ 4352               // epilogue jz stride in floats (128*34)

// ---- device-global scratch ----
// A blob: [i][mh][chunk][part(4:Ah,Al,Wh,Wl)][t(8)][lane(32)] x uint4 (8 fp16)
__device__ uint4 g_Aw4[5 * 2 * 16 * 4 * 8 * 32];
// B blob: [j][b][stile(32)][chunk][hl(2)][n8(4)][lane(32)] x uint2 (4 fp16)
__device__ uint2 g_Bf2[(size_t)5 * 4 * 32 * 16 * 2 * 4 * 32];

__device__ __forceinline__ uint32_t pack2h(float a, float b) {
    __half2 h = __floats2half2_rn(a, b);
    return *(uint32_t*)&h;
}
__device__ __forceinline__ void split16(float v, float& h, float& l) {
    __half hh = __float2half_rn(v);
    h = __half2float(hh);
    l = v - h;
}

#define MMA16(d, a, b)                                                            \
    asm volatile(                                                                 \
        "mma.sync.aligned.m16n8k16.row.col.f32.f16.f16.f32 "                      \
        "{%0,%1,%2,%3},{%4,%5,%6,%7},{%8,%9},{%0,%1,%2,%3};"                      \
        : "+f"((d)[0]), "+f"((d)[1]), "+f"((d)[2]), "+f"((d)[3])                  \
        : "r"((a).x), "r"((a).y), "r"((a).z), "r"((a).w), "r"((b).x), "r"((b).y))

// ---- prep 1: conv_w -> fragment-ordered fp16 hi/lo A(=W1+W2) and W2 ----
__global__ void prep_w(const float* __restrict__ conv_w) {
    int g = blockIdx.x * 256 + threadIdx.x;
    if (g >= 5 * 2 * 16 * 8 * 32) return;
    int lane = g & 31, t = (g >> 5) & 7, chunk = (g >> 8) & 15;
    int mh = (g >> 12) & 1, i = g >> 13;
    int r0 = mh * 128 + t * 16 + (lane >> 2), r1 = r0 + 8;
    int k0 = chunk * 16 + (lane & 3) * 2;

    float ah[2][4], al[2][4], wh[2][4], wl[2][4];
#pragma unroll
    for (int rr = 0; rr < 2; rr++) {
        int c = rr ? r1 : r0;
#pragma unroll
        for (int kk = 0; kk < 4; kk++) {
            int k = k0 + (kk & 1) + (kk >> 1) * 8;
            float w1 = conv_w[((i * CC + c) << 9) + k];
            float w2 = conv_w[((i * CC + c) << 9) + CC + k];
            split16(w1 + w2, ah[rr][kk], al[rr][kk]);
            split16(w2, wh[rr][kk], wl[rr][kk]);
        }
    }
    size_t base = ((size_t)(((i * 2 + mh) * 16 + chunk) * 4) * 8 + t) * 32 + lane;
    // part stride = 8*32 = 256 uint4
    g_Aw4[base] = make_uint4(pack2h(ah[0][0], ah[0][1]), pack2h(ah[1][0], ah[1][1]),
                             pack2h(ah[0][2], ah[0][3]), pack2h(ah[1][2], ah[1][3]));
    g_Aw4[base + 256] = make_uint4(pack2h(al[0][0], al[0][1]), pack2h(al[1][0], al[1][1]),
                                   pack2h(al[0][2], al[0][3]), pack2h(al[1][2], al[1][3]));
    g_Aw4[base + 512] = make_uint4(pack2h(wh[0][0], wh[0][1]), pack2h(wh[1][0], wh[1][1]),
                                   pack2h(wh[0][2], wh[0][3]), pack2h(wh[1][2], wh[1][3]));
    g_Aw4[base + 768] = make_uint4(pack2h(wl[0][0], wl[0][1]), pack2h(wl[1][0], wl[1][1]),
                                   pack2h(wl[0][2], wl[0][3]), pack2h(wl[1][2], wl[1][3]));
}

// ---- prep 2: x -> fragment-ordered fp16 hi/lo B ----
__global__ void prep_x(const float* __restrict__ x) {
    int g = blockIdx.x * 256 + threadIdx.x;
    if (g >= 5 * 4 * 32 * 16 * 4 * 32) return;
    int lane = g & 31, n8 = (g >> 5) & 3, chunk = (g >> 7) & 15;
    int stile = (g >> 11) & 31, b = (g >> 16) & 3, j = g >> 18;
    int n = stile * 32 + n8 * 8 + (lane >> 2);
    int k0 = chunk * 16 + (lane & 3) * 2;
    const float* px = x + (size_t)((j * BB + b) * CC) * SSZ + n;

    float h[4], l[4];
#pragma unroll
    for (int kk = 0; kk < 4; kk++) {
        int k = k0 + (kk & 1) + (kk >> 1) * 8;
        split16(px[(size_t)k * SSZ], h[kk], l[kk]);
    }
    size_t base = ((size_t)(((j * BB + b) * 32 + stile) * 16 + chunk) * 2 * 4 + n8) * 32 + lane;
    // hl stride = 4*32 = 128 uint2
    g_Bf2[base]       = make_uint2(pack2h(h[0], h[1]), pack2h(h[2], h[3]));
    g_Bf2[base + 128] = make_uint2(pack2h(l[0], l[1]), pack2h(l[2], l[3]));
}

// ---- main fused kernel: 384 threads, 12 warps = jz(6) x m-quarter(2) ----
__device__ __forceinline__ void issue_chunk(int kc, char* smc, int tid,
                                            int i, int mh, int b, int stile) {
    char* dstbase = smc + (kc % 3) * STG_B;
    const uint4* srcA = g_Aw4 + (size_t)((i * 2 + mh) * 16 + kc) * 1024;
#pragma unroll
    for (int r = 0; r < 5; r++) {
        int g = r * 384 + tid;
        if (g >= 1664) break;
        const uint4* src;
        if (g < 1024) {
            src = srcA + g;
        } else {
            int gb = g - 1024;
            int j = gb >> 7;
            src = (const uint4*)g_Bf2 +
                  (size_t)(((j * BB + b) * 32 + stile) * 16 + kc) * 128 + (gb & 127);
        }
        uint32_t dst;
        asm("{ .reg .u64 t; cvta.to.shared.u64 t, %1; cvt.u32.u64 %0, t; }"
            : "=r"(dst) : "l"(dstbase + (size_t)g * 16));
        asm volatile("cp.async.cg.shared.global [%0], [%1], 16;" :: "r"(dst), "l"(src) : "memory");
    }
    asm volatile("cp.async.commit_group;" ::: "memory");
}

__global__ __launch_bounds__(384, 1) void fused_mma(
    const float* __restrict__ x, const float* __restrict__ w5,
    const float* __restrict__ conv_b, float* __restrict__ out) {
    extern __shared__ char smc[];
    float* smf = (float*)smc;
    const int tid = threadIdx.x, wid = tid >> 5, lane = tid & 31;
    const int bx = blockIdx.x;
    const int mh = bx & 1;
    const int stile = (bx >> 1) & 31;
    const int b = (bx >> 6) & 3;
    const int i = bx >> 8;
    const int s0 = stile * 32;

    const int jz = wid >> 1;            // 0..5 (5 = Z term via W2)
    const int mq = wid & 1;             // m-quarter within this CTA's 128 rows
    const int jsel = (jz < 5) ? jz : i;
    const int p0 = (jz == 5) ? 2 : 0;   // part base: Ah/Al or Wh/Wl

    float acc[4][4][4];
#pragma unroll
    for (int t = 0; t < 4; t++)
#pragma unroll
        for (int n8 = 0; n8 < 4; n8++)
#pragma unroll
            for (int r = 0; r < 4; r++) acc[t][n8][r] = 0.0f;

    issue_chunk(0, smc, tid, i, mh, b, stile);
    issue_chunk(1, smc, tid, i, mh, b, stile);

#pragma unroll 1
    for (int kc = 0; kc < NCH; kc++) {
        if (kc + 2 < NCH) {
            issue_chunk(kc + 2, smc, tid, i, mh, b, stile);
            asm volatile("cp.async.wait_group 2;" ::: "memory");
        } else if (kc + 1 < NCH) {
            asm volatile("cp.async.wait_group 1;" ::: "memory");
        } else {
            asm volatile("cp.async.wait_group 0;" ::: "memory");
        }
        __syncthreads();

        const char* st = smc + (kc % 3) * STG_B;
        const uint2* Bp = (const uint2*)(st + 16384 + jsel * 2048);
        uint2 bh[4], bl[4];
#pragma unroll
        for (int n8 = 0; n8 < 4; n8++) {
            bh[n8] = Bp[n8 * 32 + lane];
            bl[n8] = Bp[128 + n8 * 32 + lane];
        }
        const uint4* Ap = (const uint4*)st;
        uint4 ah[4], al[4];
#pragma unroll
        for (int t = 0; t < 4; t++) {
            ah[t] = Ap[p0 * 256 + (mq * 4 + t) * 32 + lane];
            al[t] = Ap[(p0 + 1) * 256 + (mq * 4 + t) * 32 + lane];
        }
#pragma unroll
        for (int t = 0; t < 4; t++) {
#pragma unroll
            for (int n8 = 0; n8 < 4; n8++) {
                MMA16(acc[t][n8], ah[t], bh[n8]);
                MMA16(acc[t][n8], al[t], bh[n8]);
                MMA16(acc[t][n8], ah[t], bl[n8]);
            }
        }
        __syncthreads();
    }

    // ---- epilogue: stage accums to smem (stride-34 pad), then fuse ----
#pragma unroll
    for (int t = 0; t < 4; t++) {
        int c0 = mq * 64 + t * 16 + (lane >> 2);
#pragma unroll
        for (int n8 = 0; n8 < 4; n8++) {
            int s = n8 * 8 + (lane & 3) * 2;
            *(float2*)&smf[jz * EPJ + c0 * 34 + s] = make_float2(acc[t][n8][0], acc[t][n8][1]);
            *(float2*)&smf[jz * EPJ + (c0 + 8) * 34 + s] = make_float2(acc[t][n8][2], acc[t][n8][3]);
        }
    }
    __syncthreads();

    float wrow[NN];
#pragma unroll
    for (int j = 0; j < NN; j++) wrow[j] = w5[i * NN + j];

#pragma unroll 1
    for (int e = tid; e < 4096; e += 384) {
        int s_l = e & 31, c_l = e >> 5;
        int c = mh * 128 + c_l;
        float z = smf[5 * EPJ + c_l * 34 + s_l];
        float bic = conv_b[i * CC + c];
        float num = 0.0f, n2 = 0.0f;
#pragma unroll
        for (int j = 0; j < NN; j++) {
            float xx = x[(size_t)((j * BB + b) * CC + c) * SSZ + s0 + s_l];
            float y = smf[j * EPJ + c_l * 34 + s_l];
            float d = xx - (y + z + bic);
            float tt = d * wrow[j];
            float ee = 1.0f / (1.0f + expf(-tt));
            ee = (ee > 0.3f) ? ee : 0.0f;
            n2 = fmaf(ee, ee, n2);
            num = fmaf(ee, xx, num);
        }
        out[(size_t)((i * BB + b) * CC + c) * SSZ + s0 + s_l] =
            (n2 > 0.0f) ? num * rsqrtf(n2) : 0.0f;
    }
}

extern "C" void kernel_launch(void* const* d_in, const int* in_sizes, int n_in,
                              void* d_out, int out_size) {
    const float* x = nullptr;
    const float* w = nullptr;
    const float* conv_w = nullptr;
    const float* conv_b = nullptr;
    for (int t = 0; t < n_in; t++) {
        switch (in_sizes[t]) {
            case 5242880: x = (const float*)d_in[t]; break;
            case 25:      w = (const float*)d_in[t]; break;
            case 655360:  conv_w = (const float*)d_in[t]; break;
            case 1280:    conv_b = (const float*)d_in[t]; break;
            default: break;
        }
    }
    float* out = (float*)d_out;

    static bool attr_set = false;
    if (!attr_set) {
        cudaFuncSetAttribute(fused_mma, cudaFuncAttributeMaxDynamicSharedMemorySize, SMEM_BYTES);
        attr_set = true;
    }

    prep_w<<<(5 * 2 * 16 * 8 * 32 + 255) / 256, 256>>>(conv_w);
    prep_x<<<(5 * 4 * 32 * 16 * 4 * 32 + 255) / 256, 256>>>(x);
    fused_mma<<<NN * BB * 32 * 2, 384, SMEM_BYTES>>>(x, w, conv_b, out);
}

// round 11
// speedup vs baseline: 1.6042x; 1.5336x over previous
#include <cuda_runtime.h>
#include <cuda_fp16.h>
#include <cstdint>
#include <math.h>

#define NN 5
#define BB 4
#define CC 256
#define SSZ 1024
#define NCH 16                 // K=256 in k16 chunks
#define STG_B 13312            // bytes/stage: A 8192 + B 5120
#define SMEM_BYTES 52224       // epilogue staging 6*64*34*4 >= 3*STG_B
#define EPJ 2176               // 64*34 floats per jz slab
#define T0 (-0.8472978604f)    // logit(0.3)
#define MD 1.2e-3f             // flag margin on d (~5.5 sigma of fp16 GEMM error)

// ---- device-global scratch ----
// A blob: [i][mh][chunk][part(2:Ah,Wh)][t(8)][lane(32)] x uint4 (8 fp16)
__device__ uint4 g_Aw4[5 * 2 * 16 * 2 * 8 * 32];
// B blob: [j][b][stile(32)][chunk][n8(4)][lane(32)] x uint2 (4 fp16)
__device__ uint2 g_Bf2[(size_t)5 * 4 * 32 * 16 * 4 * 32];

__device__ __forceinline__ uint32_t pack2h(float a, float b) {
    __half2 h = __floats2half2_rn(a, b);
    return *(uint32_t*)&h;
}

#define MMA16(d, a, b)                                                            \
    asm volatile(                                                                 \
        "mma.sync.aligned.m16n8k16.row.col.f32.f16.f16.f32 "                      \
        "{%0,%1,%2,%3},{%4,%5,%6,%7},{%8,%9},{%0,%1,%2,%3};"                      \
        : "+f"((d)[0]), "+f"((d)[1]), "+f"((d)[2]), "+f"((d)[3])                  \
        : "r"((a).x), "r"((a).y), "r"((a).z), "r"((a).w), "r"((b).x), "r"((b).y))

// ---- prep 1: conv_w -> fragment-ordered fp16 A(=W1+W2) and W2 ----
__global__ void prep_w(const float* __restrict__ conv_w) {
    int g = blockIdx.x * 256 + threadIdx.x;
    if (g >= 5 * 2 * 16 * 8 * 32) return;
    int lane = g & 31, t = (g >> 5) & 7, chunk = (g >> 8) & 15;
    int mh = (g >> 12) & 1, i = g >> 13;
    int r0 = mh * 128 + t * 16 + (lane >> 2), r1 = r0 + 8;
    int k0 = chunk * 16 + (lane & 3) * 2;

    float av[2][4], wv[2][4];
#pragma unroll
    for (int rr = 0; rr < 2; rr++) {
        int c = rr ? r1 : r0;
#pragma unroll
        for (int kk = 0; kk < 4; kk++) {
            int k = k0 + (kk & 1) + (kk >> 1) * 8;
            float w1 = conv_w[((i * CC + c) << 9) + k];
            float w2 = conv_w[((i * CC + c) << 9) + CC + k];
            av[rr][kk] = w1 + w2;
            wv[rr][kk] = w2;
        }
    }
    size_t base = ((size_t)(((i * 2 + mh) * 16 + chunk) * 2) * 8 + t) * 32 + lane;
    g_Aw4[base] = make_uint4(pack2h(av[0][0], av[0][1]), pack2h(av[1][0], av[1][1]),
                             pack2h(av[0][2], av[0][3]), pack2h(av[1][2], av[1][3]));
    g_Aw4[base + 256] = make_uint4(pack2h(wv[0][0], wv[0][1]), pack2h(wv[1][0], wv[1][1]),
                                   pack2h(wv[0][2], wv[0][3]), pack2h(wv[1][2], wv[1][3]));
}

// ---- prep 2: x -> fragment-ordered fp16 B ----
__global__ void prep_x(const float* __restrict__ x) {
    int g = blockIdx.x * 256 + threadIdx.x;
    if (g >= 5 * 4 * 32 * 16 * 4 * 32) return;
    int lane = g & 31, n8 = (g >> 5) & 3, chunk = (g >> 7) & 15;
    int stile = (g >> 11) & 31, b = (g >> 16) & 3, j = g >> 18;
    int n = stile * 32 + n8 * 8 + (lane >> 2);
    int k0 = chunk * 16 + (lane & 3) * 2;
    const float* px = x + (size_t)((j * BB + b) * CC) * SSZ + n;
    float h[4];
#pragma unroll
    for (int kk = 0; kk < 4; kk++) {
        int k = k0 + (kk & 1) + (kk >> 1) * 8;
        h[kk] = px[(size_t)k * SSZ];
    }
    size_t base = ((size_t)((((j * BB + b) * 32 + stile) * 16 + chunk) * 4) + n8) * 32 + lane;
    g_Bf2[base] = make_uint2(pack2h(h[0], h[1]), pack2h(h[2], h[3]));
}

// ---- main fused kernel: 384 threads, 12 warps = jz(6) x m-quarter(2) ----
__device__ __forceinline__ void issue_chunk(int kc, char* smc, int tid,
                                            int i, int mh, int b, int stile) {
    char* dstbase = smc + (kc % 3) * STG_B;
    const uint4* srcA = g_Aw4 + (size_t)((i * 2 + mh) * 16 + kc) * 512;
#pragma unroll
    for (int r = 0; r < 3; r++) {
        int g = r * 384 + tid;                    // 0..831 (16B each)
        if (g >= 832) break;
        const uint4* src;
        if (g < 512) {
            src = srcA + g;
        } else {
            int gb = g - 512;
            int j = gb >> 6;
            src = (const uint4*)g_Bf2 +
                  (size_t)((((j * BB + b) * 32 + stile) * 16 + kc)) * 64 + (gb & 63);
        }
        uint32_t dst;
        asm("{ .reg .u64 t; cvta.to.shared.u64 t, %1; cvt.u32.u64 %0, t; }"
            : "=r"(dst) : "l"(dstbase + (size_t)g * 16));
        asm volatile("cp.async.cg.shared.global [%0], [%1], 16;" :: "r"(dst), "l"(src) : "memory");
    }
    asm volatile("cp.async.commit_group;" ::: "memory");
}

__global__ __launch_bounds__(384, 1) void fused_mma(
    const float* __restrict__ x, const float* __restrict__ w5,
    const float* __restrict__ conv_b, const float* __restrict__ conv_w,
    float* __restrict__ out) {
    extern __shared__ char smc[];
    float* smf = (float*)smc;
    const int tid = threadIdx.x, wid = tid >> 5, lane = tid & 31;
    const int bx = blockIdx.x;
    const int mh = bx & 1;
    const int stile = (bx >> 1) & 31;
    const int b = (bx >> 6) & 3;
    const int i = bx >> 8;
    const int s0 = stile * 32;

    const int jz = wid >> 1;            // 0..5 (5 = Z term via W2)
    const int mq = wid & 1;             // m-quarter within this CTA's 128 rows
    const int jsel = (jz < 5) ? jz : i;
    const int p0 = (jz == 5) ? 1 : 0;   // part: A or W2

    float acc[4][4][4];
#pragma unroll
    for (int t = 0; t < 4; t++)
#pragma unroll
        for (int n8 = 0; n8 < 4; n8++)
#pragma unroll
            for (int r = 0; r < 4; r++) acc[t][n8][r] = 0.0f;

    issue_chunk(0, smc, tid, i, mh, b, stile);
    issue_chunk(1, smc, tid, i, mh, b, stile);

#pragma unroll 1
    for (int kc = 0; kc < NCH; kc++) {
        if (kc + 2 < NCH) {
            issue_chunk(kc + 2, smc, tid, i, mh, b, stile);
            asm volatile("cp.async.wait_group 2;" ::: "memory");
        } else if (kc + 1 < NCH) {
            asm volatile("cp.async.wait_group 1;" ::: "memory");
        } else {
            asm volatile("cp.async.wait_group 0;" ::: "memory");
        }
        __syncthreads();

        const char* st = smc + (kc % 3) * STG_B;
        const uint2* Bp = (const uint2*)(st + 8192) + jsel * 128;
        uint2 bh[4];
#pragma unroll
        for (int n8 = 0; n8 < 4; n8++) bh[n8] = Bp[n8 * 32 + lane];
        const uint4* Ap = (const uint4*)st;
        uint4 ah[4];
#pragma unroll
        for (int t = 0; t < 4; t++) ah[t] = Ap[p0 * 256 + (mq * 4 + t) * 32 + lane];
#pragma unroll
        for (int t = 0; t < 4; t++)
#pragma unroll
            for (int n8 = 0; n8 < 4; n8++) MMA16(acc[t][n8], ah[t], bh[n8]);
        __syncthreads();
    }

    // ---- epilogue: two phases over m-quarters; exact fp32 fix-up near threshold ----
    float wrow[NN];
#pragma unroll
    for (int j = 0; j < NN; j++) wrow[j] = w5[i * NN + j];

#pragma unroll 1
    for (int ph = 0; ph < 2; ph++) {
        if (mq == ph) {
#pragma unroll
            for (int t = 0; t < 4; t++) {
                int c0 = t * 16 + (lane >> 2);
#pragma unroll
                for (int n8 = 0; n8 < 4; n8++) {
                    int s = n8 * 8 + (lane & 3) * 2;
                    *(float2*)&smf[jz * EPJ + c0 * 34 + s] =
                        make_float2(acc[t][n8][0], acc[t][n8][1]);
                    *(float2*)&smf[jz * EPJ + (c0 + 8) * 34 + s] =
                        make_float2(acc[t][n8][2], acc[t][n8][3]);
                }
            }
        }
        __syncthreads();

#pragma unroll 1
        for (int it = 0; it < 6; it++) {
            int e = it * 384 + tid;
            bool active = e < 2048;
            int s_l = e & 31;
            int c_l = active ? (e >> 5) : 0;
            int c = mh * 128 + ph * 64 + c_l;
            float z = smf[5 * EPJ + c_l * 34 + s_l];
            float bic = conv_b[i * CC + c];
            float num = 0.0f, n2 = 0.0f;
#pragma unroll 1
            for (int j = 0; j < NN; j++) {
                float wj = wrow[j];
                float xx = active ? x[(size_t)((j * BB + b) * CC + c) * SSZ + s0 + s_l] : 0.0f;
                float y = smf[j * EPJ + c_l * 34 + s_l];
                float d = xx - (y + z + bic);
                float tt = d * wj;
                float ee = 1.0f / (1.0f + expf(-tt));

                bool flg = active && (fabsf(tt - T0) < fabsf(wj) * MD);
                unsigned msk = __ballot_sync(0xffffffffu, flg);
                while (msk) {
                    int srcl = __ffs(msk) - 1;
                    msk &= msk - 1;
                    int fc = __shfl_sync(0xffffffffu, c, srcl);
                    int fs = __shfl_sync(0xffffffffu, s0 + s_l, srcl);
                    float Y = 0.0f, Z = 0.0f;
                    const float* cw = conv_w + ((size_t)(i * CC + fc) << 9);
#pragma unroll
                    for (int q = 0; q < 8; q++) {
                        int k = q * 32 + lane;
                        float a1 = cw[k], a2 = cw[CC + k];
                        float xj = x[(size_t)((j * BB + b) * CC + k) * SSZ + fs];
                        float xi = x[(size_t)((i * BB + b) * CC + k) * SSZ + fs];
                        Y = fmaf(a1 + a2, xj, Y);
                        Z = fmaf(a2, xi, Z);
                    }
                    float v = Y + Z;
#pragma unroll
                    for (int off = 16; off > 0; off >>= 1)
                        v += __shfl_xor_sync(0xffffffffu, v, off);
                    if (lane == srcl) {
                        float de = xx - (v + bic);
                        ee = 1.0f / (1.0f + expf(-de * wj));
                    }
                }
                ee = (ee > 0.3f) ? ee : 0.0f;
                n2 = fmaf(ee, ee, n2);
                num = fmaf(ee, xx, num);
            }
            if (active)
                out[(size_t)((i * BB + b) * CC + c) * SSZ + s0 + s_l] =
                    (n2 > 0.0f) ? num * rsqrtf(n2) : 0.0f;
        }
        __syncthreads();
    }
}

extern "C" void kernel_launch(void* const* d_in, const int* in_sizes, int n_in,
                              void* d_out, int out_size) {
    const float* x = nullptr;
    const float* w = nullptr;
    const float* conv_w = nullptr;
    const float* conv_b = nullptr;
    for (int t = 0; t < n_in; t++) {
        switch (in_sizes[t]) {
            case 5242880: x = (const float*)d_in[t]; break;
            case 25:      w = (const float*)d_in[t]; break;
            case 655360:  conv_w = (const float*)d_in[t]; break;
            case 1280:    conv_b = (const float*)d_in[t]; break;
            default: break;
        }
    }
    float* out = (float*)d_out;

    static bool attr_set = false;
    if (!attr_set) {
        cudaFuncSetAttribute(fused_mma, cudaFuncAttributeMaxDynamicSharedMemorySize, SMEM_BYTES);
        attr_set = true;
    }

    prep_w<<<(5 * 2 * 16 * 8 * 32 + 255) / 256, 256>>>(conv_w);
    prep_x<<<(5 * 4 * 32 * 16 * 4 * 32 + 255) / 256, 256>>>(x);
    fused_mma<<<NN * BB * 32 * 2, 384, SMEM_BYTES>>>(x, w, conv_b, conv_w, out);
}

// round 13
// speedup vs baseline: 2.3542x; 1.4676x over previous
#include <cuda_runtime.h>
#include <cuda_fp16.h>
#include <cstdint>
#include <math.h>

#define NN 5
#define BB 4
#define CC 256
#define SSZ 1024
#define NST 8                  // K=256 in k32 stages
#define SUB_B 13312            // bytes per k16 sub-block: A 8192 + B 5120
#define STG_B (2 * SUB_B)      // 26624 bytes per stage
#define SMEM_BYTES 104448      // epilogue staging 6*128*34*4 (>= 3*STG_B=79872)
#define EPJ 4352               // 128*34 floats per jz slab
#define T0 (-0.8472978604f)    // logit(0.3)
#define MD 1.2e-3f             // flag margin on d (~5.5 sigma of fp16 GEMM error)

// ---- device-global scratch ----
// A blob: [i][mh][chunk16][part(2:Ah,Wh)][t(8)][lane(32)] x uint4 (8 fp16)
__device__ uint4 g_Aw4[5 * 2 * 16 * 2 * 8 * 32];
// B blob: [j][b][stile(32)][chunk16][n8(4)][lane(32)] x uint2 (4 fp16)
__device__ uint2 g_Bf2[(size_t)5 * 4 * 32 * 16 * 4 * 32];

__device__ __forceinline__ uint32_t pack2h(float a, float b) {
    __half2 h = __floats2half2_rn(a, b);
    return *(uint32_t*)&h;
}

#define MMA16(d, a, b)                                                            \
    asm volatile(                                                                 \
        "mma.sync.aligned.m16n8k16.row.col.f32.f16.f16.f32 "                      \
        "{%0,%1,%2,%3},{%4,%5,%6,%7},{%8,%9},{%0,%1,%2,%3};"                      \
        : "+f"((d)[0]), "+f"((d)[1]), "+f"((d)[2]), "+f"((d)[3])                  \
        : "r"((a).x), "r"((a).y), "r"((a).z), "r"((a).w), "r"((b).x), "r"((b).y))

// ---- prep 1: conv_w -> fragment-ordered fp16 A(=W1+W2) and W2 ----
__global__ void prep_w(const float* __restrict__ conv_w) {
    int g = blockIdx.x * 256 + threadIdx.x;
    if (g >= 5 * 2 * 16 * 8 * 32) return;
    int lane = g & 31, t = (g >> 5) & 7, chunk = (g >> 8) & 15;
    int mh = (g >> 12) & 1, i = g >> 13;
    int r0 = mh * 128 + t * 16 + (lane >> 2), r1 = r0 + 8;
    int k0 = chunk * 16 + (lane & 3) * 2;

    float av[2][4], wv[2][4];
#pragma unroll
    for (int rr = 0; rr < 2; rr++) {
        int c = rr ? r1 : r0;
#pragma unroll
        for (int kk = 0; kk < 4; kk++) {
            int k = k0 + (kk & 1) + (kk >> 1) * 8;
            float w1 = conv_w[((i * CC + c) << 9) + k];
            float w2 = conv_w[((i * CC + c) << 9) + CC + k];
            av[rr][kk] = w1 + w2;
            wv[rr][kk] = w2;
        }
    }
    size_t base = ((size_t)(((i * 2 + mh) * 16 + chunk) * 2) * 8 + t) * 32 + lane;
    g_Aw4[base] = make_uint4(pack2h(av[0][0], av[0][1]), pack2h(av[1][0], av[1][1]),
                             pack2h(av[0][2], av[0][3]), pack2h(av[1][2], av[1][3]));
    g_Aw4[base + 256] = make_uint4(pack2h(wv[0][0], wv[0][1]), pack2h(wv[1][0], wv[1][1]),
                                   pack2h(wv[0][2], wv[0][3]), pack2h(wv[1][2], wv[1][3]));
}

// ---- prep 2: x -> fragment-ordered fp16 B ----
__global__ void prep_x(const float* __restrict__ x) {
    int g = blockIdx.x * 256 + threadIdx.x;
    if (g >= 5 * 4 * 32 * 16 * 4 * 32) return;
    int lane = g & 31, n8 = (g >> 5) & 3, chunk = (g >> 7) & 15;
    int stile = (g >> 11) & 31, b = (g >> 16) & 3, j = g >> 18;
    int n = stile * 32 + n8 * 8 + (lane >> 2);
    int k0 = chunk * 16 + (lane & 3) * 2;
    const float* px = x + (size_t)((j * BB + b) * CC) * SSZ + n;
    float h[4];
#pragma unroll
    for (int kk = 0; kk < 4; kk++) {
        int k = k0 + (kk & 1) + (kk >> 1) * 8;
        h[kk] = px[(size_t)k * SSZ];
    }
    size_t base = ((size_t)((((j * BB + b) * 32 + stile) * 16 + chunk) * 4) + n8) * 32 + lane;
    g_Bf2[base] = make_uint2(pack2h(h[0], h[1]), pack2h(h[2], h[3]));
}

// ---- main fused kernel: 384 threads, 12 warps = jz(6) x m-quarter(2) ----
__device__ __forceinline__ void issue_stage(int st, char* smc, int tid,
                                            int i, int mh, int b, int stile) {
    char* dstbase = smc + (st % 3) * STG_B;
#pragma unroll
    for (int r = 0; r < 5; r++) {
        int g = r * 384 + tid;                    // 0..1663 (16B each)
        if (g >= 1664) break;
        int sub = (g >= 832);
        int gs = g - sub * 832;
        int ck = st * 2 + sub;                    // k16 chunk index
        const uint4* src;
        if (gs < 512) {
            src = g_Aw4 + (size_t)((i * 2 + mh) * 16 + ck) * 512 + gs;
        } else {
            int gb = gs - 512;
            int j = gb >> 6;
            src = (const uint4*)g_Bf2 +
                  (size_t)((((j * BB + b) * 32 + stile) * 16 + ck)) * 64 + (gb & 63);
        }
        uint32_t dst;
        asm("{ .reg .u64 t; cvta.to.shared.u64 t, %1; cvt.u32.u64 %0, t; }"
            : "=r"(dst) : "l"(dstbase + sub * SUB_B + (size_t)gs * 16));
        asm volatile("cp.async.cg.shared.global [%0], [%1], 16;" :: "r"(dst), "l"(src) : "memory");
    }
    asm volatile("cp.async.commit_group;" ::: "memory");
}

__global__ __launch_bounds__(384, 1) void fused_mma(
    const float* __restrict__ x, const float* __restrict__ w5,
    const float* __restrict__ conv_b, const float* __restrict__ conv_w,
    float* __restrict__ out) {
    extern __shared__ char smc[];
    float* smf = (float*)smc;
    const int tid = threadIdx.x, wid = tid >> 5, lane = tid & 31;
    const int bx = blockIdx.x;
    const int mh = bx & 1;
    const int stile = (bx >> 1) & 31;
    const int b = (bx >> 6) & 3;
    const int i = bx >> 8;
    const int s0 = stile * 32;

    const int jz = wid >> 1;            // 0..5 (5 = Z term via W2)
    const int mq = wid & 1;             // m-quarter within this CTA's 128 rows
    const int jsel = (jz < 5) ? jz : i;
    const int p0 = (jz == 5) ? 1 : 0;   // part: A or W2

    float acc[4][4][4];
#pragma unroll
    for (int t = 0; t < 4; t++)
#pragma unroll
        for (int n8 = 0; n8 < 4; n8++)
#pragma unroll
            for (int r = 0; r < 4; r++) acc[t][n8][r] = 0.0f;

    issue_stage(0, smc, tid, i, mh, b, stile);
    issue_stage(1, smc, tid, i, mh, b, stile);

#pragma unroll 1
    for (int st = 0; st < NST; st++) {
        if (st + 2 < NST) {
            issue_stage(st + 2, smc, tid, i, mh, b, stile);
            asm volatile("cp.async.wait_group 2;" ::: "memory");
        } else if (st + 1 < NST) {
            asm volatile("cp.async.wait_group 1;" ::: "memory");
        } else {
            asm volatile("cp.async.wait_group 0;" ::: "memory");
        }
        __syncthreads();

#pragma unroll
        for (int kk = 0; kk < 2; kk++) {
            const char* sp = smc + (st % 3) * STG_B + kk * SUB_B;
            const uint2* Bp = (const uint2*)(sp + 8192) + jsel * 128;
            uint2 bh[4];
#pragma unroll
            for (int n8 = 0; n8 < 4; n8++) bh[n8] = Bp[n8 * 32 + lane];
            const uint4* Ap = (const uint4*)sp;
            uint4 ah[4];
#pragma unroll
            for (int t = 0; t < 4; t++) ah[t] = Ap[p0 * 256 + (mq * 4 + t) * 32 + lane];
#pragma unroll
            for (int t = 0; t < 4; t++)
#pragma unroll
                for (int n8 = 0; n8 < 4; n8++) MMA16(acc[t][n8], ah[t], bh[n8]);
        }
        __syncthreads();
    }

    // ---- epilogue: single phase; exact fp32 fix-up near threshold ----
    float wrow[NN];
#pragma unroll
    for (int j = 0; j < NN; j++) wrow[j] = w5[i * NN + j];

#pragma unroll
    for (int t = 0; t < 4; t++) {
        int c0 = mq * 64 + t * 16 + (lane >> 2);
#pragma unroll
        for (int n8 = 0; n8 < 4; n8++) {
            int s = n8 * 8 + (lane & 3) * 2;
            *(float2*)&smf[jz * EPJ + c0 * 34 + s] = make_float2(acc[t][n8][0], acc[t][n8][1]);
            *(float2*)&smf[jz * EPJ + (c0 + 8) * 34 + s] = make_float2(acc[t][n8][2], acc[t][n8][3]);
        }
    }
    __syncthreads();

#pragma unroll 1
    for (int e = tid; e < 4096; e += 384) {     // warp-uniform trip counts
        int s_l = e & 31, c_l = e >> 5;
        int c = mh * 128 + c_l;
        float z = smf[5 * EPJ + c_l * 34 + s_l];
        float bic = conv_b[i * CC + c];

        float xs[NN];
#pragma unroll
        for (int j = 0; j < NN; j++)
            xs[j] = x[(size_t)((j * BB + b) * CC + c) * SSZ + s0 + s_l];

        float num = 0.0f, n2 = 0.0f;
#pragma unroll
        for (int j = 0; j < NN; j++) {
            float wj = wrow[j];
            float xx = xs[j];
            float y = smf[j * EPJ + c_l * 34 + s_l];
            float d = xx - (y + z + bic);
            float tt = d * wj;
            float ee = 1.0f / (1.0f + expf(-tt));

            bool flg = (fabsf(tt - T0) < fabsf(wj) * MD);
            unsigned msk = __ballot_sync(0xffffffffu, flg);
            while (msk) {
                int srcl = __ffs(msk) - 1;
                msk &= msk - 1;
                int fc = __shfl_sync(0xffffffffu, c, srcl);
                int fs = __shfl_sync(0xffffffffu, s0 + s_l, srcl);
                float Y = 0.0f, Z = 0.0f;
                const float* cw = conv_w + ((size_t)(i * CC + fc) << 9);
#pragma unroll
                for (int q = 0; q < 8; q++) {
                    int k = q * 32 + lane;
                    float a1 = cw[k], a2 = cw[CC + k];
                    float xj = x[(size_t)((j * BB + b) * CC + k) * SSZ + fs];
                    float xi = x[(size_t)((i * BB + b) * CC + k) * SSZ + fs];
                    Y = fmaf(a1 + a2, xj, Y);
                    Z = fmaf(a2, xi, Z);
                }
                float v = Y + Z;
#pragma unroll
                for (int off = 16; off > 0; off >>= 1)
                    v += __shfl_xor_sync(0xffffffffu, v, off);
                if (lane == srcl) {
                    float de = xx - (v + bic);
                    ee = 1.0f / (1.0f + expf(-de * wj));
                }
            }
            ee = (ee > 0.3f) ? ee : 0.0f;
            n2 = fmaf(ee, ee, n2);
            num = fmaf(ee, xx, num);
        }
        out[(size_t)((i * BB + b) * CC + c) * SSZ + s0 + s_l] =
            (n2 > 0.0f) ? num * rsqrtf(n2) : 0.0f;
    }
}

extern "C" void kernel_launch(void* const* d_in, const int* in_sizes, int n_in,
                              void* d_out, int out_size) {
    const float* x = nullptr;
    const float* w = nullptr;
    const float* conv_w = nullptr;
    const float* conv_b = nullptr;
    for (int t = 0; t < n_in; t++) {
        switch (in_sizes[t]) {
            case 5242880: x = (const float*)d_in[t]; break;
            case 25:      w = (const float*)d_in[t]; break;
            case 655360:  conv_w = (const float*)d_in[t]; break;
            case 1280:    conv_b = (const float*)d_in[t]; break;
            default: break;
        }
    }
    float* out = (float*)d_out;

    static bool attr_set = false;
    if (!attr_set) {
        cudaFuncSetAttribute(fused_mma, cudaFuncAttributeMaxDynamicSharedMemorySize, SMEM_BYTES);
        attr_set = true;
    }

    prep_w<<<(5 * 2 * 16 * 8 * 32 + 255) / 256, 256>>>(conv_w);
    prep_x<<<(5 * 4 * 32 * 16 * 4 * 32 + 255) / 256, 256>>>(x);
    fused_mma<<<NN * BB * 32 * 2, 384, SMEM_BYTES>>>(x, w, conv_b, conv_w, out);
}

// round 16
// speedup vs baseline: 2.6275x; 1.1161x over previous
#include <cuda_runtime.h>
#include <cuda_fp16.h>
#include <cstdint>
#include <math.h>

#define NN 5
#define BB 4
#define CC 256
#define SSZ 1024
#define NST 8                  // K=256 in k32 stages
#define SUB_B 13312            // bytes per k16 sub-block: A 8192 + B 5120
#define STG_B (2 * SUB_B)      // 26624 bytes per stage
#define SMEM_BYTES 104448      // epilogue staging 6*128*34*4 (>= 3*STG_B=79872)
#define EPJ 4352               // 128*34 floats per jz slab
#define T0 (-0.8472978604f)    // logit(0.3)
#define MD 1.2e-3f             // flag margin on d (~5.5 sigma of fp16 GEMM error)

// ---- device-global scratch ----
// A blob: [i][mh][chunk16][part(2:Ah,Wh)][t(8)][lane(32)] x uint4 (8 fp16)
__device__ uint4 g_Aw4[5 * 2 * 16 * 2 * 8 * 32];
// B blob: [j][b][stile(32)][chunk16][n8(4)][lane(32)] x uint2 (4 fp16)
__device__ uint2 g_Bf2[(size_t)5 * 4 * 32 * 16 * 4 * 32];

__device__ __forceinline__ uint32_t pack2h(float a, float b) {
    __half2 h = __floats2half2_rn(a, b);
    return *(uint32_t*)&h;
}

#define MMA16(d, a, b)                                                            \
    asm volatile(                                                                 \
        "mma.sync.aligned.m16n8k16.row.col.f32.f16.f16.f32 "                      \
        "{%0,%1,%2,%3},{%4,%5,%6,%7},{%8,%9},{%0,%1,%2,%3};"                      \
        : "+f"((d)[0]), "+f"((d)[1]), "+f"((d)[2]), "+f"((d)[3])                  \
        : "r"((a).x), "r"((a).y), "r"((a).z), "r"((a).w), "r"((b).x), "r"((b).y))

// ---- prep 1: conv_w -> fragment-ordered fp16 A(=W1+W2) and W2 ----
__global__ void prep_w(const float* __restrict__ conv_w) {
    int g = blockIdx.x * 256 + threadIdx.x;
    if (g >= 5 * 2 * 16 * 8 * 32) return;
    int lane = g & 31, t = (g >> 5) & 7, chunk = (g >> 8) & 15;
    int mh = (g >> 12) & 1, i = g >> 13;
    int r0 = mh * 128 + t * 16 + (lane >> 2), r1 = r0 + 8;
    int k0 = chunk * 16 + (lane & 3) * 2;

    float av[2][4], wv[2][4];
#pragma unroll
    for (int rr = 0; rr < 2; rr++) {
        int c = rr ? r1 : r0;
#pragma unroll
        for (int kk = 0; kk < 4; kk++) {
            int k = k0 + (kk & 1) + (kk >> 1) * 8;
            float w1 = conv_w[((i * CC + c) << 9) + k];
            float w2 = conv_w[((i * CC + c) << 9) + CC + k];
            av[rr][kk] = w1 + w2;
            wv[rr][kk] = w2;
        }
    }
    size_t base = ((size_t)(((i * 2 + mh) * 16 + chunk) * 2) * 8 + t) * 32 + lane;
    g_Aw4[base] = make_uint4(pack2h(av[0][0], av[0][1]), pack2h(av[1][0], av[1][1]),
                             pack2h(av[0][2], av[0][3]), pack2h(av[1][2], av[1][3]));
    g_Aw4[base + 256] = make_uint4(pack2h(wv[0][0], wv[0][1]), pack2h(wv[1][0], wv[1][1]),
                                   pack2h(wv[0][2], wv[0][3]), pack2h(wv[1][2], wv[1][3]));
}

// ---- prep 2: x -> fragment-ordered fp16 B ----
__global__ void prep_x(const float* __restrict__ x) {
    int g = blockIdx.x * 256 + threadIdx.x;
    if (g >= 5 * 4 * 32 * 16 * 4 * 32) return;
    int lane = g & 31, n8 = (g >> 5) & 3, chunk = (g >> 7) & 15;
    int stile = (g >> 11) & 31, b = (g >> 16) & 3, j = g >> 18;
    int n = stile * 32 + n8 * 8 + (lane >> 2);
    int k0 = chunk * 16 + (lane & 3) * 2;
    const float* px = x + (size_t)((j * BB + b) * CC) * SSZ + n;
    float h[4];
#pragma unroll
    for (int kk = 0; kk < 4; kk++) {
        int k = k0 + (kk & 1) + (kk >> 1) * 8;
        h[kk] = px[(size_t)k * SSZ];
    }
    size_t base = ((size_t)((((j * BB + b) * 32 + stile) * 16 + chunk) * 4) + n8) * 32 + lane;
    g_Bf2[base] = make_uint2(pack2h(h[0], h[1]), pack2h(h[2], h[3]));
}

// ---- main fused kernel: 384 threads, 12 warps = jz(6) x m-quarter(2) ----
__device__ __forceinline__ void issue_stage(int st, char* smc, int tid,
                                            int i, int mh, int b, int stile) {
    char* dstbase = smc + (st % 3) * STG_B;
#pragma unroll
    for (int r = 0; r < 5; r++) {
        int g = r * 384 + tid;                    // 0..1663 (16B each)
        if (g >= 1664) break;
        int sub = (g >= 832);
        int gs = g - sub * 832;
        int ck = st * 2 + sub;                    // k16 chunk index
        const uint4* src;
        if (gs < 512) {
            src = g_Aw4 + (size_t)((i * 2 + mh) * 16 + ck) * 512 + gs;
        } else {
            int gb = gs - 512;
            int j = gb >> 6;
            src = (const uint4*)g_Bf2 +
                  (size_t)((((j * BB + b) * 32 + stile) * 16 + ck)) * 64 + (gb & 63);
        }
        uint32_t dst;
        asm("{ .reg .u64 t; cvta.to.shared.u64 t, %1; cvt.u32.u64 %0, t; }"
            : "=r"(dst) : "l"(dstbase + sub * SUB_B + (size_t)gs * 16));
        asm volatile("cp.async.cg.shared.global [%0], [%1], 16;" :: "r"(dst), "l"(src) : "memory");
    }
    asm volatile("cp.async.commit_group;" ::: "memory");
}

__global__ __launch_bounds__(384, 1) void fused_mma(
    const float* __restrict__ x, const float* __restrict__ w5,
    const float* __restrict__ conv_b, const float* __restrict__ conv_w,
    float* __restrict__ out) {
    extern __shared__ char smc[];
    float* smf = (float*)smc;
    const int tid = threadIdx.x, wid = tid >> 5, lane = tid & 31;
    const int bx = blockIdx.x;
    const int mh = bx & 1;
    const int stile = (bx >> 1) & 31;
    const int b = (bx >> 6) & 3;
    const int i = bx >> 8;
    const int s0 = stile * 32;

    const int jz = wid >> 1;            // 0..5 (5 = Z term via W2)
    const int mq = wid & 1;             // m-quarter within this CTA's 128 rows
    const int jsel = (jz < 5) ? jz : i;
    const int p0 = (jz == 5) ? 1 : 0;   // part: A or W2

    float acc[4][4][4];
#pragma unroll
    for (int t = 0; t < 4; t++)
#pragma unroll
        for (int n8 = 0; n8 < 4; n8++)
#pragma unroll
            for (int r = 0; r < 4; r++) acc[t][n8][r] = 0.0f;

    issue_stage(0, smc, tid, i, mh, b, stile);
    issue_stage(1, smc, tid, i, mh, b, stile);

#pragma unroll 1
    for (int st = 0; st < NST; st++) {
        // wait for stage st's cp.async group; at most 1 newer group may remain
        if (st < NST - 1) {
            asm volatile("cp.async.wait_group 1;" ::: "memory");
        } else {
            asm volatile("cp.async.wait_group 0;" ::: "memory");
        }
        __syncthreads();   // also proves compute(st-1) done in all warps -> safe to overwrite its buffer
        if (st + 2 < NST) issue_stage(st + 2, smc, tid, i, mh, b, stile);

#pragma unroll
        for (int kk = 0; kk < 2; kk++) {
            const char* sp = smc + (st % 3) * STG_B + kk * SUB_B;
            const uint2* Bp = (const uint2*)(sp + 8192) + jsel * 128;
            uint2 bh[4];
#pragma unroll
            for (int n8 = 0; n8 < 4; n8++) bh[n8] = Bp[n8 * 32 + lane];
            const uint4* Ap = (const uint4*)sp;
            uint4 ah[4];
#pragma unroll
            for (int t = 0; t < 4; t++) ah[t] = Ap[p0 * 256 + (mq * 4 + t) * 32 + lane];
#pragma unroll
            for (int t = 0; t < 4; t++)
#pragma unroll
                for (int n8 = 0; n8 < 4; n8++) MMA16(acc[t][n8], ah[t], bh[n8]);
        }
    }
    __syncthreads();   // mainloop done; smem stages can be reused for epilogue staging

    // ---- epilogue: single phase; fast sigmoid; exact fp32 fix-up near threshold ----
    float wrow[NN];
#pragma unroll
    for (int j = 0; j < NN; j++) wrow[j] = w5[i * NN + j];

#pragma unroll
    for (int t = 0; t < 4; t++) {
        int c0 = mq * 64 + t * 16 + (lane >> 2);
#pragma unroll
        for (int n8 = 0; n8 < 4; n8++) {
            int s = n8 * 8 + (lane & 3) * 2;
            *(float2*)&smf[jz * EPJ + c0 * 34 + s] = make_float2(acc[t][n8][0], acc[t][n8][1]);
            *(float2*)&smf[jz * EPJ + (c0 + 8) * 34 + s] = make_float2(acc[t][n8][2], acc[t][n8][3]);
        }
    }
    __syncthreads();

#pragma unroll 1
    for (int e = tid; e < 4096; e += 384) {     // warp-uniform trip counts
        int s_l = e & 31, c_l = e >> 5;
        int c = mh * 128 + c_l;
        float z = smf[5 * EPJ + c_l * 34 + s_l];
        float bic = conv_b[i * CC + c];

        float xs[NN];
#pragma unroll
        for (int j = 0; j < NN; j++)
            xs[j] = x[(size_t)((j * BB + b) * CC + c) * SSZ + s0 + s_l];

        float num = 0.0f, n2 = 0.0f;
#pragma unroll
        for (int j = 0; j < NN; j++) {
            float wj = wrow[j];
            float xx = xs[j];
            float y = smf[j * EPJ + c_l * 34 + s_l];
            float d = xx - (y + z + bic);
            float tt = d * wj;
            float ee = __fdividef(1.0f, 1.0f + __expf(-tt));   // fast sigmoid

            bool flg = (fabsf(tt - T0) < fabsf(wj) * MD);
            unsigned msk = __ballot_sync(0xffffffffu, flg);
            while (msk) {
                int srcl = __ffs(msk) - 1;
                msk &= msk - 1;
                int fc = __shfl_sync(0xffffffffu, c, srcl);
                int fs = __shfl_sync(0xffffffffu, s0 + s_l, srcl);
                float Y = 0.0f, Z = 0.0f;
                const float* cw = conv_w + ((size_t)(i * CC + fc) << 9);
#pragma unroll
                for (int q = 0; q < 8; q++) {
                    int k = q * 32 + lane;
                    float a1 = cw[k], a2 = cw[CC + k];
                    float xj = x[(size_t)((j * BB + b) * CC + k) * SSZ + fs];
                    float xi = x[(size_t)((i * BB + b) * CC + k) * SSZ + fs];
                    Y = fmaf(a1 + a2, xj, Y);
                    Z = fmaf(a2, xi, Z);
                }
                float v = Y + Z;
#pragma unroll
                for (int off = 16; off > 0; off >>= 1)
                    v += __shfl_xor_sync(0xffffffffu, v, off);
                if (lane == srcl) {
                    float de = xx - (v + bic);
                    ee = 1.0f / (1.0f + expf(-de * wj));       // precise on repaired path
                }
            }
            ee = (ee > 0.3f) ? ee : 0.0f;
            n2 = fmaf(ee, ee, n2);
            num = fmaf(ee, xx, num);
        }
        out[(size_t)((i * BB + b) * CC + c) * SSZ + s0 + s_l] =
            (n2 > 0.0f) ? num * rsqrtf(n2) : 0.0f;
    }
}

extern "C" void kernel_launch(void* const* d_in, const int* in_sizes, int n_in,
                              void* d_out, int out_size) {
    const float* x = nullptr;
    const float* w = nullptr;
    const float* conv_w = nullptr;
    const float* conv_b = nullptr;
    for (int t = 0; t < n_in; t++) {
        switch (in_sizes[t]) {
            case 5242880: x = (const float*)d_in[t]; break;
            case 25:      w = (const float*)d_in[t]; break;
            case 655360:  conv_w = (const float*)d_in[t]; break;
            case 1280:    conv_b = (const float*)d_in[t]; break;
            default: break;
        }
    }
    float* out = (float*)d_out;

    static bool attr_set = false;
    if (!attr_set) {
        cudaFuncSetAttribute(fused_mma, cudaFuncAttributeMaxDynamicSharedMemorySize, SMEM_BYTES);
        attr_set = true;
    }

    prep_w<<<(5 * 2 * 16 * 8 * 32 + 255) / 256, 256>>>(conv_w);
    prep_x<<<(5 * 4 * 32 * 16 * 4 * 32 + 255) / 256, 256>>>(x);
    fused_mma<<<NN * BB * 32 * 2, 384, SMEM_BYTES>>>(x, w, conv_b, conv_w, out);
}